// round 6
// baseline (speedup 1.0000x reference)
#include <cuda_runtime.h>
#include <cuda_fp16.h>
#include <mma.h>
#include <cstdint>

using namespace nvcuda;

// ---------------------------------------------------------------------------
// Problem constants
// ---------------------------------------------------------------------------
#define N_ROWS 8192
#define K_IN   4096
#define M_OUT  4096
#define R_LORA 16
#define KP     4160          // 4096 + 1 bias col + 63 zero pad = 65*64
#define NCHUNK 65            // KP / 64
#define SCALING 2.0f

// Scratch (device globals — no runtime allocation). ~103 MB total.
__device__ __half g_x[(size_t)N_ROWS * KP];
__device__ __half g_w[(size_t)M_OUT * KP];

// ---------------------------------------------------------------------------
// Kernel 1: W_eff = W + 2*B@A, packed to fp16.   (folds LoRA into weights)
// ---------------------------------------------------------------------------
#define WEFF_KO 32
#define WEFF_KK 512

__global__ __launch_bounds__(256) void weff_pack_kernel(
        const float* __restrict__ W,
        const float* __restrict__ loraA,
        const float* __restrict__ loraB) {
    __shared__ float sA[16][WEFF_KK + 8];
    __shared__ float sB[WEFF_KO][17];
    const int tid = threadIdx.x;
    const int kbase = blockIdx.x * WEFF_KK;
    const int obase = blockIdx.y * WEFF_KO;

    for (int i = tid; i < 16 * (WEFF_KK / 4); i += 256) {
        const int r  = i / (WEFF_KK / 4);
        const int c4 = i % (WEFF_KK / 4);
        *(float4*)&sA[r][c4 * 4] =
            *(const float4*)&loraA[(size_t)r * K_IN + kbase + c4 * 4];
    }
    for (int i = tid; i < WEFF_KO * 16; i += 256) {
        const int o = i >> 4, r = i & 15;
        sB[o][r] = SCALING * loraB[(size_t)(obase + o) * R_LORA + r];
    }
    __syncthreads();

    const int kq = tid & 63;
    const int og = tid >> 6;

    float acc[8][8];
    #pragma unroll
    for (int i = 0; i < 8; i++)
        #pragma unroll
        for (int j = 0; j < 8; j++)
            acc[i][j] = 0.f;

    #pragma unroll 4
    for (int r = 0; r < 16; r++) {
        float a[8];
        #pragma unroll
        for (int j = 0; j < 8; j++) a[j] = sA[r][kq * 8 + j];
        #pragma unroll
        for (int oo = 0; oo < 8; oo++) {
            const float bv = sB[og * 8 + oo][r];
            #pragma unroll
            for (int j = 0; j < 8; j++) acc[oo][j] += bv * a[j];
        }
    }

    #pragma unroll
    for (int oo = 0; oo < 8; oo++) {
        const int o = obase + og * 8 + oo;
        const size_t gk = (size_t)o * K_IN + kbase + kq * 8;
        const float4 w0 = *(const float4*)&W[gk];
        const float4 w1 = *(const float4*)&W[gk + 4];
        __half h[8];
        h[0] = __float2half_rn(w0.x + acc[oo][0]);
        h[1] = __float2half_rn(w0.y + acc[oo][1]);
        h[2] = __float2half_rn(w0.z + acc[oo][2]);
        h[3] = __float2half_rn(w0.w + acc[oo][3]);
        h[4] = __float2half_rn(w1.x + acc[oo][4]);
        h[5] = __float2half_rn(w1.y + acc[oo][5]);
        h[6] = __float2half_rn(w1.z + acc[oo][6]);
        h[7] = __float2half_rn(w1.w + acc[oo][7]);
        *(uint4*)&g_w[(size_t)o * KP + kbase + kq * 8] = *(const uint4*)h;
    }
}

// Tail columns [4096, 4160) of g_w: bias at 4096, zeros elsewhere.
__global__ void pack_w_tail(const float* __restrict__ b) {
    const int idx = blockIdx.x * blockDim.x + threadIdx.x;
    const int o = idx >> 6;
    const int c = idx & 63;
    if (o >= M_OUT) return;
    const float v = (c == 0) ? b[o] : 0.f;
    g_w[(size_t)o * KP + K_IN + c] = __float2half_rn(v);
}

// ---------------------------------------------------------------------------
// Kernel 2: pack x into fp16 augmented rows: [x | 1 | 0...].
// ---------------------------------------------------------------------------
#define C8_PER_ROW (KP / 8)   // 520

__global__ void pack_x_kernel(const float* __restrict__ x) {
    const size_t idx = (size_t)blockIdx.x * blockDim.x + threadIdx.x;
    const int row = (int)(idx / C8_PER_ROW);
    const int c8  = (int)(idx % C8_PER_ROW);
    if (row >= N_ROWS) return;
    __half h[8];
    if (c8 < K_IN / 8) {
        const float4 v0 = *(const float4*)&x[(size_t)row * K_IN + c8 * 8];
        const float4 v1 = *(const float4*)&x[(size_t)row * K_IN + c8 * 8 + 4];
        h[0] = __float2half_rn(v0.x); h[1] = __float2half_rn(v0.y);
        h[2] = __float2half_rn(v0.z); h[3] = __float2half_rn(v0.w);
        h[4] = __float2half_rn(v1.x); h[5] = __float2half_rn(v1.y);
        h[6] = __float2half_rn(v1.z); h[7] = __float2half_rn(v1.w);
    } else {
        #pragma unroll
        for (int j = 0; j < 8; j++) {
            const int k = c8 * 8 + j;
            h[j] = __float2half_rn(k == K_IN ? 1.0f : 0.0f);
        }
    }
    *(uint4*)&g_x[(size_t)row * KP + c8 * 8] = *(const uint4*)h;
}

// ---------------------------------------------------------------------------
// Kernel 3: fp16 GEMM.
// CTA tile 128(M) x 256(N), BK=64, **512 threads / 16 warps** (4Mx4N),
// warp tile 32x64. 4-stage cp.async pipeline, 144B pitch (conflict-free).
// B fragments streamed to keep regs under the 128/thread RF cap.
// ---------------------------------------------------------------------------
#define BM 128
#define BN 256
#define BK 64
#define STAGES 4
#define PITCH 72                                  // halves per row (144 B)
#define XTILE_HALFS (BM * PITCH)                  // 9216
#define WTILE_HALFS (BN * PITCH)                  // 18432
#define STAGE_HALFS (XTILE_HALFS + WTILE_HALFS)   // 27648
#define SMEM_BYTES (STAGES * STAGE_HALFS * 2)     // 221184

__device__ __forceinline__ uint32_t smem_u32(const void* p) {
    return (uint32_t)__cvta_generic_to_shared(p);
}

__global__ __launch_bounds__(512, 1) void gemm_fp16(float* __restrict__ out) {
    extern __shared__ __align__(16) __half smem[];
    const int tid  = threadIdx.x;
    const int warp = tid >> 5;
    const int wm = warp >> 2;       // 0..3 -> M offset wm*32
    const int wn = warp & 3;        // 0..3 -> N offset wn*64

    // Grouped raster: 8 M-tiles x 16 N-tiles (~1 wave) for L2 locality.
    const int NUM_N = M_OUT / BN;   // 16
    const int GRP = 8;
    const int per = GRP * NUM_N;    // 128
    const int pid = blockIdx.x;
    const int gid = pid / per;
    const int rem = pid % per;
    const int mt = gid * GRP + (rem % GRP);
    const int nt = rem / GRP;
    const size_t rowM = (size_t)mt * BM;
    const size_t rowN = (size_t)nt * BN;

    // ---- chunk loader: 3072 16B-chunks, 6 cp.async per thread ----
    auto load_chunk = [&](int j, int s) {
        __half* sbase = smem + s * STAGE_HALFS;
        const int k0 = j * BK;
        #pragma unroll
        for (int t = 0; t < 6; t++) {
            const int ch = t * 512 + tid;          // 0..3071
            const __half* g;
            uint32_t sa;
            if (ch < 1024) {                       // X tile: 128 rows x 8 chunks
                const int r = ch >> 3, c = ch & 7;
                g  = g_x + (rowM + r) * KP + k0 + c * 8;
                sa = smem_u32(sbase + r * PITCH + c * 8);
            } else {                               // W tile: 256 rows x 8 chunks
                const int idx = ch - 1024;
                const int r = idx >> 3, c = idx & 7;
                g  = g_w + (rowN + r) * KP + k0 + c * 8;
                sa = smem_u32(sbase + XTILE_HALFS + r * PITCH + c * 8);
            }
            asm volatile("cp.async.cg.shared.global [%0], [%1], 16;"
                         :: "r"(sa), "l"(g) : "memory");
        }
        asm volatile("cp.async.commit_group;" ::: "memory");
    };

    wmma::fragment<wmma::accumulator, 16, 16, 16, float> acc[2][4];
    #pragma unroll
    for (int m = 0; m < 2; m++)
        #pragma unroll
        for (int n = 0; n < 4; n++)
            wmma::fill_fragment(acc[m][n], 0.0f);

    #pragma unroll
    for (int s = 0; s < STAGES - 1; s++) load_chunk(s, s);

    for (int i = 0; i < NCHUNK; i++) {
        asm volatile("cp.async.wait_group %0;" :: "n"(STAGES - 2) : "memory");
        __syncthreads();

        const int j = i + STAGES - 1;
        if (j < NCHUNK) load_chunk(j, j % STAGES);

        const __half* sX = smem + (i % STAGES) * STAGE_HALFS;
        const __half* sW = sX + XTILE_HALFS;

        #pragma unroll
        for (int ks = 0; ks < 4; ks++) {
            wmma::fragment<wmma::matrix_a, 16, 16, 16, __half, wmma::row_major> a[2];
            #pragma unroll
            for (int m = 0; m < 2; m++)
                wmma::load_matrix_sync(a[m], sX + (wm * 32 + m * 16) * PITCH + ks * 16, PITCH);
            #pragma unroll
            for (int n = 0; n < 4; n++) {
                wmma::fragment<wmma::matrix_b, 16, 16, 16, __half, wmma::col_major> bf;
                wmma::load_matrix_sync(bf, sW + (wn * 64 + n * 16) * PITCH + ks * 16, PITCH);
                #pragma unroll
                for (int m = 0; m < 2; m++)
                    wmma::mma_sync(acc[m][n], a[m], bf, acc[m][n]);
            }
        }
    }

    // Epilogue: direct stores (each output element written exactly once)
    #pragma unroll
    for (int m = 0; m < 2; m++)
        #pragma unroll
        for (int n = 0; n < 4; n++) {
            float* dst = &out[(rowM + wm * 32 + m * 16) * M_OUT +
                              rowN + wn * 64 + n * 16];
            wmma::store_matrix_sync(dst, acc[m][n], M_OUT, wmma::mem_row_major);
        }
}

// ---------------------------------------------------------------------------
// Launch
// ---------------------------------------------------------------------------
extern "C" void kernel_launch(void* const* d_in, const int* in_sizes, int n_in,
                              void* d_out, int out_size) {
    const float* x     = (const float*)d_in[0];
    const float* W     = (const float*)d_in[1];
    const float* b     = (const float*)d_in[2];
    const float* loraA = (const float*)d_in[3];
    const float* loraB = (const float*)d_in[4];
    float* out = (float*)d_out;

    dim3 wg(K_IN / WEFF_KK, M_OUT / WEFF_KO);   // (8, 128)
    weff_pack_kernel<<<wg, 256>>>(W, loraA, loraB);
    pack_w_tail<<<(M_OUT * 64) / 256, 256>>>(b);

    const int px = (int)(((size_t)N_ROWS * C8_PER_ROW + 511) / 512);
    pack_x_kernel<<<px, 512>>>(x);

    static bool attr_set = false;
    if (!attr_set) {
        cudaFuncSetAttribute(gemm_fp16, cudaFuncAttributeMaxDynamicSharedMemorySize,
                             SMEM_BYTES);
        attr_set = true;
    }
    const int num_tiles = (N_ROWS / BM) * (M_OUT / BN);   // 1024
    gemm_fp16<<<num_tiles, 512, SMEM_BYTES>>>(out);
}

// round 8
// speedup vs baseline: 1.0405x; 1.0405x over previous
#include <cuda_runtime.h>
#include <cuda_fp16.h>
#include <cstdint>

// ---------------------------------------------------------------------------
// Problem constants
// ---------------------------------------------------------------------------
#define N_ROWS 8192
#define K_IN   4096
#define M_OUT  4096
#define R_LORA 16
#define KP     4160          // 4096 + 1 bias col + 63 zero pad = 65*64
#define NCHUNK 65            // KP / 64
#define SCALING 2.0f

// Scratch (device globals — no runtime allocation). ~103 MB total.
__device__ __half g_x[(size_t)N_ROWS * KP];
__device__ __half g_w[(size_t)M_OUT * KP];

// ---------------------------------------------------------------------------
// Kernel 1: W_eff = W + 2*B@A, packed to fp16.   (folds LoRA into weights)
// ---------------------------------------------------------------------------
#define WEFF_KO 32
#define WEFF_KK 512

__global__ __launch_bounds__(256) void weff_pack_kernel(
        const float* __restrict__ W,
        const float* __restrict__ loraA,
        const float* __restrict__ loraB) {
    __shared__ float sA[16][WEFF_KK + 8];
    __shared__ float sB[WEFF_KO][17];
    const int tid = threadIdx.x;
    const int kbase = blockIdx.x * WEFF_KK;
    const int obase = blockIdx.y * WEFF_KO;

    for (int i = tid; i < 16 * (WEFF_KK / 4); i += 256) {
        const int r  = i / (WEFF_KK / 4);
        const int c4 = i % (WEFF_KK / 4);
        *(float4*)&sA[r][c4 * 4] =
            *(const float4*)&loraA[(size_t)r * K_IN + kbase + c4 * 4];
    }
    for (int i = tid; i < WEFF_KO * 16; i += 256) {
        const int o = i >> 4, r = i & 15;
        sB[o][r] = SCALING * loraB[(size_t)(obase + o) * R_LORA + r];
    }
    __syncthreads();

    const int kq = tid & 63;
    const int og = tid >> 6;

    float acc[8][8];
    #pragma unroll
    for (int i = 0; i < 8; i++)
        #pragma unroll
        for (int j = 0; j < 8; j++)
            acc[i][j] = 0.f;

    #pragma unroll 4
    for (int r = 0; r < 16; r++) {
        float a[8];
        #pragma unroll
        for (int j = 0; j < 8; j++) a[j] = sA[r][kq * 8 + j];
        #pragma unroll
        for (int oo = 0; oo < 8; oo++) {
            const float bv = sB[og * 8 + oo][r];
            #pragma unroll
            for (int j = 0; j < 8; j++) acc[oo][j] += bv * a[j];
        }
    }

    #pragma unroll
    for (int oo = 0; oo < 8; oo++) {
        const int o = obase + og * 8 + oo;
        const size_t gk = (size_t)o * K_IN + kbase + kq * 8;
        const float4 w0 = *(const float4*)&W[gk];
        const float4 w1 = *(const float4*)&W[gk + 4];
        __half h[8];
        h[0] = __float2half_rn(w0.x + acc[oo][0]);
        h[1] = __float2half_rn(w0.y + acc[oo][1]);
        h[2] = __float2half_rn(w0.z + acc[oo][2]);
        h[3] = __float2half_rn(w0.w + acc[oo][3]);
        h[4] = __float2half_rn(w1.x + acc[oo][4]);
        h[5] = __float2half_rn(w1.y + acc[oo][5]);
        h[6] = __float2half_rn(w1.z + acc[oo][6]);
        h[7] = __float2half_rn(w1.w + acc[oo][7]);
        *(uint4*)&g_w[(size_t)o * KP + kbase + kq * 8] = *(const uint4*)h;
    }
}

// Tail columns [4096, 4160) of g_w: bias at 4096, zeros elsewhere.
__global__ void pack_w_tail(const float* __restrict__ b) {
    const int idx = blockIdx.x * blockDim.x + threadIdx.x;
    const int o = idx >> 6;
    const int c = idx & 63;
    if (o >= M_OUT) return;
    const float v = (c == 0) ? b[o] : 0.f;
    g_w[(size_t)o * KP + K_IN + c] = __float2half_rn(v);
}

// ---------------------------------------------------------------------------
// Kernel 2: pack x into fp16 augmented rows: [x | 1 | 0...].
// ---------------------------------------------------------------------------
#define C8_PER_ROW (KP / 8)   // 520

__global__ void pack_x_kernel(const float* __restrict__ x) {
    const size_t idx = (size_t)blockIdx.x * blockDim.x + threadIdx.x;
    const int row = (int)(idx / C8_PER_ROW);
    const int c8  = (int)(idx % C8_PER_ROW);
    if (row >= N_ROWS) return;
    __half h[8];
    if (c8 < K_IN / 8) {
        const float4 v0 = *(const float4*)&x[(size_t)row * K_IN + c8 * 8];
        const float4 v1 = *(const float4*)&x[(size_t)row * K_IN + c8 * 8 + 4];
        h[0] = __float2half_rn(v0.x); h[1] = __float2half_rn(v0.y);
        h[2] = __float2half_rn(v0.z); h[3] = __float2half_rn(v0.w);
        h[4] = __float2half_rn(v1.x); h[5] = __float2half_rn(v1.y);
        h[6] = __float2half_rn(v1.z); h[7] = __float2half_rn(v1.w);
    } else {
        #pragma unroll
        for (int j = 0; j < 8; j++) {
            const int k = c8 * 8 + j;
            h[j] = __float2half_rn(k == K_IN ? 1.0f : 0.0f);
        }
    }
    *(uint4*)&g_x[(size_t)row * KP + c8 * 8] = *(const uint4*)h;
}

// ---------------------------------------------------------------------------
// Kernel 3: fp16 GEMM — raw mma.sync.m16n8k16 + ldmatrix, fragment
// double-buffering across ks-steps.
// CTA 128(M) x 256(N), BK=64, 256 threads / 8 warps (2Mx4N), warp 64x64.
// 4-stage cp.async pipeline, 144B pitch (conflict-free ldmatrix).
// ---------------------------------------------------------------------------
#define BM 128
#define BN 256
#define BK 64
#define STAGES 4
#define PITCH 72                                  // halves per row (144 B)
#define XTILE_HALFS (BM * PITCH)                  // 9216
#define WTILE_HALFS (BN * PITCH)                  // 18432
#define STAGE_HALFS (XTILE_HALFS + WTILE_HALFS)   // 27648
#define STAGE_BYTES (STAGE_HALFS * 2)
#define SMEM_BYTES (STAGES * STAGE_BYTES)         // 221184

__device__ __forceinline__ uint32_t smem_u32(const void* p) {
    return (uint32_t)__cvta_generic_to_shared(p);
}

__device__ __forceinline__ void ldsm_x4(uint32_t* r, uint32_t addr) {
    asm volatile("ldmatrix.sync.aligned.m8n8.x4.shared.b16 {%0,%1,%2,%3}, [%4];"
                 : "=r"(r[0]), "=r"(r[1]), "=r"(r[2]), "=r"(r[3])
                 : "r"(addr));
}

__device__ __forceinline__ void mma_16816(float* c, const uint32_t* a,
                                          const uint32_t* b) {
    asm volatile("mma.sync.aligned.m16n8k16.row.col.f32.f16.f16.f32 "
                 "{%0,%1,%2,%3}, {%4,%5,%6,%7}, {%8,%9}, {%0,%1,%2,%3};"
                 : "+f"(c[0]), "+f"(c[1]), "+f"(c[2]), "+f"(c[3])
                 : "r"(a[0]), "r"(a[1]), "r"(a[2]), "r"(a[3]),
                   "r"(b[0]), "r"(b[1]));
}

__global__ __launch_bounds__(256, 1) void gemm_fp16(float* __restrict__ out) {
    extern __shared__ __align__(16) __half smem[];
    const uint32_t su = smem_u32(smem);
    const int tid  = threadIdx.x;
    const int lane = tid & 31;
    const int warp = tid >> 5;
    const int wm = warp >> 2;       // 0..1 -> M offset wm*64
    const int wn = warp & 3;        // 0..3 -> N offset wn*64

    // Grouped raster: 8 M-tiles x 16 N-tiles (~1 wave) for L2 locality.
    const int NUM_N = M_OUT / BN;   // 16
    const int GRP = 8;
    const int per = GRP * NUM_N;    // 128
    const int pid = blockIdx.x;
    const int gid = pid / per;
    const int rem = pid % per;
    const int mt = gid * GRP + (rem % GRP);
    const int nt = rem / GRP;
    const size_t rowM = (size_t)mt * BM;
    const size_t rowN = (size_t)nt * BN;

    // ---- chunk loader: 3072 16B-chunks, 12 cp.async per thread ----
    auto load_chunk = [&](int j, int s) {
        __half* sbase = smem + s * STAGE_HALFS;
        const int k0 = j * BK;
        #pragma unroll
        for (int t = 0; t < 12; t++) {
            const int ch = t * 256 + tid;          // 0..3071
            const __half* g;
            uint32_t sa;
            if (ch < 1024) {                       // X tile: 128 rows x 8 chunks
                const int r = ch >> 3, c = ch & 7;
                g  = g_x + (rowM + r) * KP + k0 + c * 8;
                sa = smem_u32(sbase + r * PITCH + c * 8);
            } else {                               // W tile: 256 rows x 8 chunks
                const int idx = ch - 1024;
                const int r = idx >> 3, c = idx & 7;
                g  = g_w + (rowN + r) * KP + k0 + c * 8;
                sa = smem_u32(sbase + XTILE_HALFS + r * PITCH + c * 8);
            }
            asm volatile("cp.async.cg.shared.global [%0], [%1], 16;"
                         :: "r"(sa), "l"(g) : "memory");
        }
        asm volatile("cp.async.commit_group;" ::: "memory");
    };

    // Per-thread ldmatrix base offsets (bytes, relative to stage base).
    // A: lanes 0-15 -> rows 0-15 (+0B), lanes 16-31 -> rows 0-15 (+16B)
    const uint32_t aOff0 = 2u * ((wm * 64 + (lane & 15)) * PITCH + (lane >> 4) * 8);
    // B: row = (lane&7) + ((lane&16)?8:0), half = (lane>>3)&1
    const uint32_t bRow = (lane & 7) + ((lane & 16) ? 8 : 0);
    const uint32_t bOff0 = 2u * (XTILE_HALFS + (wn * 64 + bRow) * PITCH +
                                 ((lane >> 3) & 1) * 8);

    float acc[4][8][4];
    #pragma unroll
    for (int m = 0; m < 4; m++)
        #pragma unroll
        for (int n = 0; n < 8; n++)
            #pragma unroll
            for (int e = 0; e < 4; e++)
                acc[m][n][e] = 0.f;

    uint32_t Af[2][4][4];   // [buf][mf][reg]
    uint32_t Bf[2][4][4];   // [buf][g][reg] — g covers nf pair (2g, 2g+1)

    auto load_frags = [&](uint32_t stageBase, int ks, int buf) {
        const uint32_t ksOff = ks * 32;            // 16 halves = 32 B
        #pragma unroll
        for (int mf = 0; mf < 4; mf++)
            ldsm_x4(Af[buf][mf], stageBase + aOff0 + mf * (16 * PITCH * 2) + ksOff);
        #pragma unroll
        for (int g = 0; g < 4; g++)
            ldsm_x4(Bf[buf][g], stageBase + bOff0 + g * (16 * PITCH * 2) + ksOff);
    };

    // Prologue: fill STAGES-1 stages
    #pragma unroll
    for (int s = 0; s < STAGES - 1; s++) load_chunk(s, s);

    for (int i = 0; i < NCHUNK; i++) {
        asm volatile("cp.async.wait_group %0;" :: "n"(STAGES - 2) : "memory");
        __syncthreads();

        const int j = i + STAGES - 1;
        if (j < NCHUNK) load_chunk(j, j % STAGES);

        const uint32_t stageBase = su + (i % STAGES) * STAGE_BYTES;

        load_frags(stageBase, 0, 0);
        #pragma unroll
        for (int ks = 0; ks < 4; ks++) {
            const int cur = ks & 1;
            if (ks < 3) load_frags(stageBase, ks + 1, cur ^ 1);
            #pragma unroll
            for (int mf = 0; mf < 4; mf++)
                #pragma unroll
                for (int g = 0; g < 4; g++) {
                    mma_16816(acc[mf][2 * g],     Af[cur][mf], &Bf[cur][g][0]);
                    mma_16816(acc[mf][2 * g + 1], Af[cur][mf], &Bf[cur][g][2]);
                }
        }
    }

    // Epilogue: direct float2 stores. Thread t: rows (t>>2) and (t>>2)+8,
    // col pair 2*(t&3) within each m16n8 tile.
    const int erow = lane >> 2;
    const int ecol = (lane & 3) * 2;
    #pragma unroll
    for (int mf = 0; mf < 4; mf++) {
        const size_t r0 = rowM + wm * 64 + mf * 16 + erow;
        #pragma unroll
        for (int nf = 0; nf < 8; nf++) {
            const size_t cc = rowN + wn * 64 + nf * 8 + ecol;
            *(float2*)&out[r0 * M_OUT + cc] =
                make_float2(acc[mf][nf][0], acc[mf][nf][1]);
            *(float2*)&out[(r0 + 8) * M_OUT + cc] =
                make_float2(acc[mf][nf][2], acc[mf][nf][3]);
        }
    }
}

// ---------------------------------------------------------------------------
// Launch
// ---------------------------------------------------------------------------
extern "C" void kernel_launch(void* const* d_in, const int* in_sizes, int n_in,
                              void* d_out, int out_size) {
    const float* x     = (const float*)d_in[0];
    const float* W     = (const float*)d_in[1];
    const float* b     = (const float*)d_in[2];
    const float* loraA = (const float*)d_in[3];
    const float* loraB = (const float*)d_in[4];
    float* out = (float*)d_out;

    dim3 wg(K_IN / WEFF_KK, M_OUT / WEFF_KO);   // (8, 128)
    weff_pack_kernel<<<wg, 256>>>(W, loraA, loraB);
    pack_w_tail<<<(M_OUT * 64) / 256, 256>>>(b);

    const int px = (int)(((size_t)N_ROWS * C8_PER_ROW + 511) / 512);
    pack_x_kernel<<<px, 512>>>(x);

    static bool attr_set = false;
    if (!attr_set) {
        cudaFuncSetAttribute(gemm_fp16, cudaFuncAttributeMaxDynamicSharedMemorySize,
                             SMEM_BYTES);
        attr_set = true;
    }
    const int num_tiles = (N_ROWS / BM) * (M_OUT / BN);   // 1024
    gemm_fp16<<<num_tiles, 256, SMEM_BYTES>>>(out);
}

// round 11
// speedup vs baseline: 1.0580x; 1.0168x over previous
#include <cuda_runtime.h>
#include <cuda_fp16.h>
#include <cstdint>

// ---------------------------------------------------------------------------
// Problem constants
// ---------------------------------------------------------------------------
#define N_ROWS 8192
#define K_IN   4096
#define M_OUT  4096
#define R_LORA 16
#define KP     4160          // 4096 + 1 bias col + 63 zero pad = 65*64
#define NCHUNK 65            // KP / 64
#define SCALING 2.0f

// Scratch (device globals — no runtime allocation). ~103 MB total.
__device__ __half g_x[(size_t)N_ROWS * KP];
__device__ __half g_w[(size_t)M_OUT * KP];

// ---------------------------------------------------------------------------
// Kernel 1: W_eff = W + 2*B@A, packed to fp16.   (folds LoRA into weights)
// ---------------------------------------------------------------------------
#define WEFF_KO 32
#define WEFF_KK 512

__global__ __launch_bounds__(256) void weff_pack_kernel(
        const float* __restrict__ W,
        const float* __restrict__ loraA,
        const float* __restrict__ loraB) {
    __shared__ float sA[16][WEFF_KK + 8];
    __shared__ float sB[WEFF_KO][17];
    const int tid = threadIdx.x;
    const int kbase = blockIdx.x * WEFF_KK;
    const int obase = blockIdx.y * WEFF_KO;

    for (int i = tid; i < 16 * (WEFF_KK / 4); i += 256) {
        const int r  = i / (WEFF_KK / 4);
        const int c4 = i % (WEFF_KK / 4);
        *(float4*)&sA[r][c4 * 4] =
            *(const float4*)&loraA[(size_t)r * K_IN + kbase + c4 * 4];
    }
    for (int i = tid; i < WEFF_KO * 16; i += 256) {
        const int o = i >> 4, r = i & 15;
        sB[o][r] = SCALING * loraB[(size_t)(obase + o) * R_LORA + r];
    }
    __syncthreads();

    const int kq = tid & 63;
    const int og = tid >> 6;

    float acc[8][8];
    #pragma unroll
    for (int i = 0; i < 8; i++)
        #pragma unroll
        for (int j = 0; j < 8; j++)
            acc[i][j] = 0.f;

    #pragma unroll 4
    for (int r = 0; r < 16; r++) {
        float a[8];
        #pragma unroll
        for (int j = 0; j < 8; j++) a[j] = sA[r][kq * 8 + j];
        #pragma unroll
        for (int oo = 0; oo < 8; oo++) {
            const float bv = sB[og * 8 + oo][r];
            #pragma unroll
            for (int j = 0; j < 8; j++) acc[oo][j] += bv * a[j];
        }
    }

    #pragma unroll
    for (int oo = 0; oo < 8; oo++) {
        const int o = obase + og * 8 + oo;
        const size_t gk = (size_t)o * K_IN + kbase + kq * 8;
        const float4 w0 = *(const float4*)&W[gk];
        const float4 w1 = *(const float4*)&W[gk + 4];
        __half h[8];
        h[0] = __float2half_rn(w0.x + acc[oo][0]);
        h[1] = __float2half_rn(w0.y + acc[oo][1]);
        h[2] = __float2half_rn(w0.z + acc[oo][2]);
        h[3] = __float2half_rn(w0.w + acc[oo][3]);
        h[4] = __float2half_rn(w1.x + acc[oo][4]);
        h[5] = __float2half_rn(w1.y + acc[oo][5]);
        h[6] = __float2half_rn(w1.z + acc[oo][6]);
        h[7] = __float2half_rn(w1.w + acc[oo][7]);
        *(uint4*)&g_w[(size_t)o * KP + kbase + kq * 8] = *(const uint4*)h;
    }
}

// Tail columns [4096, 4160) of g_w: bias at 4096, zeros elsewhere.
__global__ void pack_w_tail(const float* __restrict__ b) {
    const int idx = blockIdx.x * blockDim.x + threadIdx.x;
    const int o = idx >> 6;
    const int c = idx & 63;
    if (o >= M_OUT) return;
    const float v = (c == 0) ? b[o] : 0.f;
    g_w[(size_t)o * KP + K_IN + c] = __float2half_rn(v);
}

// ---------------------------------------------------------------------------
// Kernel 2: pack x into fp16 augmented rows: [x | 1 | 0...].
// ---------------------------------------------------------------------------
#define C8_PER_ROW (KP / 8)   // 520

__global__ void pack_x_kernel(const float* __restrict__ x) {
    const size_t idx = (size_t)blockIdx.x * blockDim.x + threadIdx.x;
    const int row = (int)(idx / C8_PER_ROW);
    const int c8  = (int)(idx % C8_PER_ROW);
    if (row >= N_ROWS) return;
    __half h[8];
    if (c8 < K_IN / 8) {
        const float4 v0 = *(const float4*)&x[(size_t)row * K_IN + c8 * 8];
        const float4 v1 = *(const float4*)&x[(size_t)row * K_IN + c8 * 8 + 4];
        h[0] = __float2half_rn(v0.x); h[1] = __float2half_rn(v0.y);
        h[2] = __float2half_rn(v0.z); h[3] = __float2half_rn(v0.w);
        h[4] = __float2half_rn(v1.x); h[5] = __float2half_rn(v1.y);
        h[6] = __float2half_rn(v1.z); h[7] = __float2half_rn(v1.w);
    } else {
        #pragma unroll
        for (int j = 0; j < 8; j++) {
            const int k = c8 * 8 + j;
            h[j] = __float2half_rn(k == K_IN ? 1.0f : 0.0f);
        }
    }
    *(uint4*)&g_x[(size_t)row * KP + c8 * 8] = *(const uint4*)h;
}

// ---------------------------------------------------------------------------
// Kernel 3: fp16 GEMM — raw mma.sync.m16n8k16 + ldmatrix, fragment
// double-buffering, **2 CTAs per SM** for barrier-bubble overlap.
// CTA 128(M) x 128(N), BK=64, 128 threads / 4 warps (2Mx2N), warp 64x64.
// 3-stage cp.async pipeline, 144B pitch (conflict-free ldmatrix).
// smem 110,592 B/CTA -> 2 resident; regs ~222 -> 57K/SM (fits 64K RF).
// ---------------------------------------------------------------------------
#define BM 128
#define BN 128
#define BK 64
#define STAGES 3
#define PITCH 72                                  // halves per row (144 B)
#define XTILE_HALFS (BM * PITCH)                  // 9216
#define WTILE_HALFS (BN * PITCH)                  // 9216
#define STAGE_HALFS (XTILE_HALFS + WTILE_HALFS)   // 18432
#define STAGE_BYTES (STAGE_HALFS * 2)             // 36864
#define SMEM_BYTES (STAGES * STAGE_BYTES)         // 110592

__device__ __forceinline__ uint32_t smem_u32(const void* p) {
    return (uint32_t)__cvta_generic_to_shared(p);
}

__device__ __forceinline__ void ldsm_x4(uint32_t* r, uint32_t addr) {
    asm volatile("ldmatrix.sync.aligned.m8n8.x4.shared.b16 {%0,%1,%2,%3}, [%4];"
                 : "=r"(r[0]), "=r"(r[1]), "=r"(r[2]), "=r"(r[3])
                 : "r"(addr));
}

__device__ __forceinline__ void mma_16816(float* c, const uint32_t* a,
                                          const uint32_t* b) {
    asm volatile("mma.sync.aligned.m16n8k16.row.col.f32.f16.f16.f32 "
                 "{%0,%1,%2,%3}, {%4,%5,%6,%7}, {%8,%9}, {%0,%1,%2,%3};"
                 : "+f"(c[0]), "+f"(c[1]), "+f"(c[2]), "+f"(c[3])
                 : "r"(a[0]), "r"(a[1]), "r"(a[2]), "r"(a[3]),
                   "r"(b[0]), "r"(b[1]));
}

__global__ __launch_bounds__(128, 2) void gemm_fp16(float* __restrict__ out) {
    extern __shared__ __align__(16) __half smem[];
    const uint32_t su = smem_u32(smem);
    const int tid  = threadIdx.x;
    const int lane = tid & 31;
    const int warp = tid >> 5;
    const int wm = warp >> 1;       // 0..1 -> M offset wm*64
    const int wn = warp & 1;        // 0..1 -> N offset wn*64

    // Grouped raster: 16 M-tiles x 32 N-tiles per group for L2 locality.
    const int NUM_N = M_OUT / BN;   // 32
    const int GRP = 16;
    const int per = GRP * NUM_N;    // 512
    const int pid = blockIdx.x;
    const int gid = pid / per;
    const int rem = pid % per;
    const int mt = gid * GRP + (rem % GRP);
    const int nt = rem / GRP;
    const size_t rowM = (size_t)mt * BM;
    const size_t rowN = (size_t)nt * BN;

    // ---- chunk loader: 2048 16B-chunks, 16 cp.async per thread ----
    auto load_chunk = [&](int j, int s) {
        __half* sbase = smem + s * STAGE_HALFS;
        const int k0 = j * BK;
        #pragma unroll
        for (int t = 0; t < 16; t++) {
            const int ch = t * 128 + tid;          // 0..2047
            const __half* g;
            uint32_t sa;
            if (ch < 1024) {                       // X tile: 128 rows x 8 chunks
                const int r = ch >> 3, c = ch & 7;
                g  = g_x + (rowM + r) * KP + k0 + c * 8;
                sa = smem_u32(sbase + r * PITCH + c * 8);
            } else {                               // W tile: 128 rows x 8 chunks
                const int idx = ch - 1024;
                const int r = idx >> 3, c = idx & 7;
                g  = g_w + (rowN + r) * KP + k0 + c * 8;
                sa = smem_u32(sbase + XTILE_HALFS + r * PITCH + c * 8);
            }
            asm volatile("cp.async.cg.shared.global [%0], [%1], 16;"
                         :: "r"(sa), "l"(g) : "memory");
        }
        asm volatile("cp.async.commit_group;" ::: "memory");
    };

    // Per-thread ldmatrix base offsets (bytes, relative to stage base).
    const uint32_t aOff0 = 2u * ((wm * 64 + (lane & 15)) * PITCH + (lane >> 4) * 8);
    const uint32_t bRow = (lane & 7) + ((lane & 16) ? 8 : 0);
    const uint32_t bOff0 = 2u * (XTILE_HALFS + (wn * 64 + bRow) * PITCH +
                                 ((lane >> 3) & 1) * 8);

    float acc[4][8][4];
    #pragma unroll
    for (int m = 0; m < 4; m++)
        #pragma unroll
        for (int n = 0; n < 8; n++)
            #pragma unroll
            for (int e = 0; e < 4; e++)
                acc[m][n][e] = 0.f;

    uint32_t Af[2][4][4];   // [buf][mf][reg]
    uint32_t Bf[2][4][4];   // [buf][g][reg] — g covers nf pair (2g, 2g+1)

    auto load_frags = [&](uint32_t stageBase, int ks, int buf) {
        const uint32_t ksOff = ks * 32;            // 16 halves = 32 B
        #pragma unroll
        for (int mf = 0; mf < 4; mf++)
            ldsm_x4(Af[buf][mf], stageBase + aOff0 + mf * (16 * PITCH * 2) + ksOff);
        #pragma unroll
        for (int g = 0; g < 4; g++)
            ldsm_x4(Bf[buf][g], stageBase + bOff0 + g * (16 * PITCH * 2) + ksOff);
    };

    // Prologue: fill STAGES-1 stages
    #pragma unroll
    for (int s = 0; s < STAGES - 1; s++) load_chunk(s, s);

    for (int i = 0; i < NCHUNK; i++) {
        asm volatile("cp.async.wait_group %0;" :: "n"(STAGES - 2) : "memory");
        __syncthreads();

        const int j = i + STAGES - 1;
        if (j < NCHUNK) load_chunk(j, j % STAGES);

        const uint32_t stageBase = su + (i % STAGES) * STAGE_BYTES;

        load_frags(stageBase, 0, 0);
        #pragma unroll
        for (int ks = 0; ks < 4; ks++) {
            const int cur = ks & 1;
            if (ks < 3) load_frags(stageBase, ks + 1, cur ^ 1);
            #pragma unroll
            for (int mf = 0; mf < 4; mf++)
                #pragma unroll
                for (int g = 0; g < 4; g++) {
                    mma_16816(acc[mf][2 * g],     Af[cur][mf], &Bf[cur][g][0]);
                    mma_16816(acc[mf][2 * g + 1], Af[cur][mf], &Bf[cur][g][2]);
                }
        }
    }

    // Epilogue: direct float2 stores.
    const int erow = lane >> 2;
    const int ecol = (lane & 3) * 2;
    #pragma unroll
    for (int mf = 0; mf < 4; mf++) {
        const size_t r0 = rowM + wm * 64 + mf * 16 + erow;
        #pragma unroll
        for (int nf = 0; nf < 8; nf++) {
            const size_t cc = rowN + wn * 64 + nf * 8 + ecol;
            *(float2*)&out[r0 * M_OUT + cc] =
                make_float2(acc[mf][nf][0], acc[mf][nf][1]);
            *(float2*)&out[(r0 + 8) * M_OUT + cc] =
                make_float2(acc[mf][nf][2], acc[mf][nf][3]);
        }
    }
}

// ---------------------------------------------------------------------------
// Launch
// ---------------------------------------------------------------------------
extern "C" void kernel_launch(void* const* d_in, const int* in_sizes, int n_in,
                              void* d_out, int out_size) {
    const float* x     = (const float*)d_in[0];
    const float* W     = (const float*)d_in[1];
    const float* b     = (const float*)d_in[2];
    const float* loraA = (const float*)d_in[3];
    const float* loraB = (const float*)d_in[4];
    float* out = (float*)d_out;

    dim3 wg(K_IN / WEFF_KK, M_OUT / WEFF_KO);   // (8, 128)
    weff_pack_kernel<<<wg, 256>>>(W, loraA, loraB);
    pack_w_tail<<<(M_OUT * 64) / 256, 256>>>(b);

    const int px = (int)(((size_t)N_ROWS * C8_PER_ROW + 511) / 512);
    pack_x_kernel<<<px, 512>>>(x);

    static bool attr_set = false;
    if (!attr_set) {
        cudaFuncSetAttribute(gemm_fp16, cudaFuncAttributeMaxDynamicSharedMemorySize,
                             SMEM_BYTES);
        attr_set = true;
    }
    const int num_tiles = (N_ROWS / BM) * (M_OUT / BN);   // 2048
    gemm_fp16<<<num_tiles, 128, SMEM_BYTES>>>(out);
}

// round 14
// speedup vs baseline: 1.4463x; 1.3670x over previous
#include <cuda_runtime.h>
#include <cuda_fp16.h>
#include <cstdint>

// ---------------------------------------------------------------------------
// Problem constants
// ---------------------------------------------------------------------------
#define N_ROWS 8192
#define K_IN   4096
#define M_OUT  4096
#define R_LORA 16
#define KP     4096          // bias handled in epilogue now
#define NCHUNK 64            // KP / 64
#define SCALING 2.0f

// Scratch (device globals — no runtime allocation). ~100 MB total.
__device__ __half g_x[(size_t)N_ROWS * KP];
__device__ __half g_w[(size_t)M_OUT * KP];

// ---------------------------------------------------------------------------
// Kernel 1: W_eff = W + 2*B@A, packed to fp16.   (folds LoRA into weights)
// ---------------------------------------------------------------------------
#define WEFF_KO 32
#define WEFF_KK 512

__global__ __launch_bounds__(256) void weff_pack_kernel(
        const float* __restrict__ W,
        const float* __restrict__ loraA,
        const float* __restrict__ loraB) {
    __shared__ float sA[16][WEFF_KK + 8];
    __shared__ float sB[WEFF_KO][17];
    const int tid = threadIdx.x;
    const int kbase = blockIdx.x * WEFF_KK;
    const int obase = blockIdx.y * WEFF_KO;

    for (int i = tid; i < 16 * (WEFF_KK / 4); i += 256) {
        const int r  = i / (WEFF_KK / 4);
        const int c4 = i % (WEFF_KK / 4);
        *(float4*)&sA[r][c4 * 4] =
            *(const float4*)&loraA[(size_t)r * K_IN + kbase + c4 * 4];
    }
    for (int i = tid; i < WEFF_KO * 16; i += 256) {
        const int o = i >> 4, r = i & 15;
        sB[o][r] = SCALING * loraB[(size_t)(obase + o) * R_LORA + r];
    }
    __syncthreads();

    const int kq = tid & 63;
    const int og = tid >> 6;

    float acc[8][8];
    #pragma unroll
    for (int i = 0; i < 8; i++)
        #pragma unroll
        for (int j = 0; j < 8; j++)
            acc[i][j] = 0.f;

    #pragma unroll 4
    for (int r = 0; r < 16; r++) {
        float a[8];
        #pragma unroll
        for (int j = 0; j < 8; j++) a[j] = sA[r][kq * 8 + j];
        #pragma unroll
        for (int oo = 0; oo < 8; oo++) {
            const float bv = sB[og * 8 + oo][r];
            #pragma unroll
            for (int j = 0; j < 8; j++) acc[oo][j] += bv * a[j];
        }
    }

    #pragma unroll
    for (int oo = 0; oo < 8; oo++) {
        const int o = obase + og * 8 + oo;
        const size_t gk = (size_t)o * K_IN + kbase + kq * 8;
        const float4 w0 = *(const float4*)&W[gk];
        const float4 w1 = *(const float4*)&W[gk + 4];
        __half h[8];
        h[0] = __float2half_rn(w0.x + acc[oo][0]);
        h[1] = __float2half_rn(w0.y + acc[oo][1]);
        h[2] = __float2half_rn(w0.z + acc[oo][2]);
        h[3] = __float2half_rn(w0.w + acc[oo][3]);
        h[4] = __float2half_rn(w1.x + acc[oo][4]);
        h[5] = __float2half_rn(w1.y + acc[oo][5]);
        h[6] = __float2half_rn(w1.z + acc[oo][6]);
        h[7] = __float2half_rn(w1.w + acc[oo][7]);
        *(uint4*)&g_w[(size_t)o * KP + kbase + kq * 8] = *(const uint4*)h;
    }
}

// ---------------------------------------------------------------------------
// Kernel 2: pack x into fp16 (pure convert, branch-free).
// ---------------------------------------------------------------------------
#define C8_PER_ROW (KP / 8)   // 512

__global__ void pack_x_kernel(const float* __restrict__ x) {
    const size_t idx = (size_t)blockIdx.x * blockDim.x + threadIdx.x;
    if (idx >= (size_t)N_ROWS * C8_PER_ROW) return;
    const size_t base = idx * 8;
    const float4 v0 = *(const float4*)&x[base];
    const float4 v1 = *(const float4*)&x[base + 4];
    __half h[8];
    h[0] = __float2half_rn(v0.x); h[1] = __float2half_rn(v0.y);
    h[2] = __float2half_rn(v0.z); h[3] = __float2half_rn(v0.w);
    h[4] = __float2half_rn(v1.x); h[5] = __float2half_rn(v1.y);
    h[6] = __float2half_rn(v1.z); h[7] = __float2half_rn(v1.w);
    *(uint4*)&g_x[base] = *(const uint4*)h;
}

// ---------------------------------------------------------------------------
// Kernel 3: fp16 GEMM — raw mma.sync.m16n8k16 + ldmatrix, fragment
// double-buffering, 2 CTAs/SM, cp.async spread across ks-steps,
// bias added in fp32 epilogue.
// CTA 128x128, BK=64, 128 threads / 4 warps (2Mx2N), warp 64x64.
// 3-stage cp.async pipeline, 144B pitch (conflict-free ldmatrix).
// ---------------------------------------------------------------------------
#define BM 128
#define BN 128
#define BK 64
#define STAGES 3
#define PITCH 72                                  // halves per row (144 B)
#define XTILE_HALFS (BM * PITCH)                  // 9216
#define WTILE_HALFS (BN * PITCH)                  // 9216
#define STAGE_HALFS (XTILE_HALFS + WTILE_HALFS)   // 18432
#define STAGE_BYTES (STAGE_HALFS * 2)             // 36864
#define SMEM_BYTES (STAGES * STAGE_BYTES)         // 110592

__device__ __forceinline__ uint32_t smem_u32(const void* p) {
    return (uint32_t)__cvta_generic_to_shared(p);
}

__device__ __forceinline__ void ldsm_x4(uint32_t* r, uint32_t addr) {
    asm volatile("ldmatrix.sync.aligned.m8n8.x4.shared.b16 {%0,%1,%2,%3}, [%4];"
                 : "=r"(r[0]), "=r"(r[1]), "=r"(r[2]), "=r"(r[3])
                 : "r"(addr));
}

__device__ __forceinline__ void mma_16816(float* c, const uint32_t* a,
                                          const uint32_t* b) {
    asm volatile("mma.sync.aligned.m16n8k16.row.col.f32.f16.f16.f32 "
                 "{%0,%1,%2,%3}, {%4,%5,%6,%7}, {%8,%9}, {%0,%1,%2,%3};"
                 : "+f"(c[0]), "+f"(c[1]), "+f"(c[2]), "+f"(c[3])
                 : "r"(a[0]), "r"(a[1]), "r"(a[2]), "r"(a[3]),
                   "r"(b[0]), "r"(b[1]));
}

__global__ __launch_bounds__(128, 2) void gemm_fp16(float* __restrict__ out,
                                                    const float* __restrict__ bias) {
    extern __shared__ __align__(16) __half smem[];
    const uint32_t su = smem_u32(smem);
    const int tid  = threadIdx.x;
    const int lane = tid & 31;
    const int warp = tid >> 5;
    const int wm = warp >> 1;       // 0..1 -> M offset wm*64
    const int wn = warp & 1;        // 0..1 -> N offset wn*64

    // Grouped raster: 16 M-tiles x 32 N-tiles per group for L2 locality.
    const int NUM_N = M_OUT / BN;   // 32
    const int GRP = 16;
    const int per = GRP * NUM_N;    // 512
    const int pid = blockIdx.x;
    const int gid = pid / per;
    const int rem = pid % per;
    const int mt = gid * GRP + (rem % GRP);
    const int nt = rem / GRP;
    const size_t rowM = (size_t)mt * BM;
    const size_t rowN = (size_t)nt * BN;

    // ---- quarter-chunk loader: 4 cp.async per thread (512 chunks of 16B) ---
    auto load_q = [&](int j, int s, int q) {
        __half* sbase = smem + s * STAGE_HALFS;
        const int k0 = j * BK;
        #pragma unroll
        for (int t = q * 4; t < q * 4 + 4; t++) {
            const int ch = t * 128 + tid;          // 0..2047
            const __half* g;
            uint32_t sa;
            if (ch < 1024) {                       // X tile: 128 rows x 8 chunks
                const int r = ch >> 3, c = ch & 7;
                g  = g_x + (rowM + r) * KP + k0 + c * 8;
                sa = smem_u32(sbase + r * PITCH + c * 8);
            } else {                               // W tile: 128 rows x 8 chunks
                const int idx = ch - 1024;
                const int r = idx >> 3, c = idx & 7;
                g  = g_w + (rowN + r) * KP + k0 + c * 8;
                sa = smem_u32(sbase + XTILE_HALFS + r * PITCH + c * 8);
            }
            asm volatile("cp.async.cg.shared.global [%0], [%1], 16;"
                         :: "r"(sa), "l"(g) : "memory");
        }
    };
    auto cp_commit = [&]() {
        asm volatile("cp.async.commit_group;" ::: "memory");
    };

    // Per-thread ldmatrix base offsets (bytes, relative to stage base).
    const uint32_t aOff0 = 2u * ((wm * 64 + (lane & 15)) * PITCH + (lane >> 4) * 8);
    const uint32_t bRow = (lane & 7) + ((lane & 16) ? 8 : 0);
    const uint32_t bOff0 = 2u * (XTILE_HALFS + (wn * 64 + bRow) * PITCH +
                                 ((lane >> 3) & 1) * 8);

    float acc[4][8][4];
    #pragma unroll
    for (int m = 0; m < 4; m++)
        #pragma unroll
        for (int n = 0; n < 8; n++)
            #pragma unroll
            for (int e = 0; e < 4; e++)
                acc[m][n][e] = 0.f;

    uint32_t Af[2][4][4];   // [buf][mf][reg]
    uint32_t Bf[2][4][4];   // [buf][g][reg]

    auto load_frags = [&](uint32_t stageBase, int ks, int buf) {
        const uint32_t ksOff = ks * 32;            // 16 halves = 32 B
        #pragma unroll
        for (int mf = 0; mf < 4; mf++)
            ldsm_x4(Af[buf][mf], stageBase + aOff0 + mf * (16 * PITCH * 2) + ksOff);
        #pragma unroll
        for (int g = 0; g < 4; g++)
            ldsm_x4(Bf[buf][g], stageBase + bOff0 + g * (16 * PITCH * 2) + ksOff);
    };

    // Prologue: fill STAGES-1 stages
    #pragma unroll
    for (int s = 0; s < STAGES - 1; s++) {
        #pragma unroll
        for (int q = 0; q < 4; q++) load_q(s, s, q);
        cp_commit();
    }

    for (int i = 0; i < NCHUNK; i++) {
        asm volatile("cp.async.wait_group %0;" :: "n"(STAGES - 2) : "memory");
        __syncthreads();

        const int j = i + STAGES - 1;              // chunk to prefetch
        const int sj = j % STAGES;
        const uint32_t stageBase = su + (i % STAGES) * STAGE_BYTES;

        load_frags(stageBase, 0, 0);
        #pragma unroll
        for (int ks = 0; ks < 4; ks++) {
            const int cur = ks & 1;
            if (j < NCHUNK) load_q(j, sj, ks);     // spread cp.async issue
            if (ks < 3) load_frags(stageBase, ks + 1, cur ^ 1);
            #pragma unroll
            for (int mf = 0; mf < 4; mf++)
                #pragma unroll
                for (int g = 0; g < 4; g++) {
                    mma_16816(acc[mf][2 * g],     Af[cur][mf], &Bf[cur][g][0]);
                    mma_16816(acc[mf][2 * g + 1], Af[cur][mf], &Bf[cur][g][2]);
                }
        }
        cp_commit();   // one group per chunk (keeps wait_group accounting)
    }

    // Epilogue: add bias (fp32) and store.
    const int erow = lane >> 2;
    const int ecol = (lane & 3) * 2;
    float2 bv[8];
    #pragma unroll
    for (int nf = 0; nf < 8; nf++) {
        const size_t cc = rowN + wn * 64 + nf * 8 + ecol;
        bv[nf] = *(const float2*)&bias[cc];
    }
    #pragma unroll
    for (int mf = 0; mf < 4; mf++) {
        const size_t r0 = rowM + wm * 64 + mf * 16 + erow;
        #pragma unroll
        for (int nf = 0; nf < 8; nf++) {
            const size_t cc = rowN + wn * 64 + nf * 8 + ecol;
            *(float2*)&out[r0 * M_OUT + cc] =
                make_float2(acc[mf][nf][0] + bv[nf].x, acc[mf][nf][1] + bv[nf].y);
            *(float2*)&out[(r0 + 8) * M_OUT + cc] =
                make_float2(acc[mf][nf][2] + bv[nf].x, acc[mf][nf][3] + bv[nf].y);
        }
    }
}

// ---------------------------------------------------------------------------
// Launch
// ---------------------------------------------------------------------------
extern "C" void kernel_launch(void* const* d_in, const int* in_sizes, int n_in,
                              void* d_out, int out_size) {
    const float* x     = (const float*)d_in[0];
    const float* W     = (const float*)d_in[1];
    const float* b     = (const float*)d_in[2];
    const float* loraA = (const float*)d_in[3];
    const float* loraB = (const float*)d_in[4];
    float* out = (float*)d_out;

    dim3 wg(K_IN / WEFF_KK, M_OUT / WEFF_KO);   // (8, 128)
    weff_pack_kernel<<<wg, 256>>>(W, loraA, loraB);

    const int px = (int)(((size_t)N_ROWS * C8_PER_ROW + 511) / 512);
    pack_x_kernel<<<px, 512>>>(x);

    static bool attr_set = false;
    if (!attr_set) {
        cudaFuncSetAttribute(gemm_fp16, cudaFuncAttributeMaxDynamicSharedMemorySize,
                             SMEM_BYTES);
        attr_set = true;
    }
    const int num_tiles = (N_ROWS / BM) * (M_OUT / BN);   // 2048
    gemm_fp16<<<num_tiles, 128, SMEM_BYTES>>>(out, b);
}